// round 1
// baseline (speedup 1.0000x reference)
#include <cuda_runtime.h>
#include <cstdint>

#define NU 100000
#define NI 100000
#define D  128

typedef unsigned long long u64;

// ---------------- scratch (static device allocation; no cudaMalloc) ----------
__device__ float g_acc_f [(size_t)NU * D];   // follows:  user -> user
__device__ float g_acc_rb[(size_t)NU * D];   // ratedby:  item -> user
__device__ float g_acc_r [(size_t)NI * D];   // rates:    user -> item
__device__ int   g_cnt_f [NU];
__device__ int   g_cnt_rb[NU];
__device__ int   g_cnt_r [NI];

// ---------------- zero scratch ----------------------------------------------
__global__ void zero_kernel() {
    const size_t n4 = (size_t)NU * D / 4;   // float4 count per acc array
    float4 z = make_float4(0.f, 0.f, 0.f, 0.f);
    size_t stride = (size_t)gridDim.x * blockDim.x;
    for (size_t i = (size_t)blockIdx.x * blockDim.x + threadIdx.x; i < n4; i += stride) {
        reinterpret_cast<float4*>(g_acc_f )[i] = z;
        reinterpret_cast<float4*>(g_acc_rb)[i] = z;
        reinterpret_cast<float4*>(g_acc_r )[i] = z;
    }
    for (size_t i = (size_t)blockIdx.x * blockDim.x + threadIdx.x; i < NU; i += stride) {
        g_cnt_f[i] = 0; g_cnt_rb[i] = 0; g_cnt_r[i] = 0;
    }
}

// ---------------- edge scatter: acc[dst] += feat[src], cnt[dst]++ ------------
// one warp per edge; each lane handles 4 consecutive floats (float4 gather,
// 4 scalar f32 atomics -> RED.E.ADD to L2, 128B contiguous per warp)
__global__ __launch_bounds__(256) void scatter_kernel(
    const float4* __restrict__ feat, const int* __restrict__ src,
    const int* __restrict__ dst, float* __restrict__ acc,
    int* __restrict__ cnt, int E)
{
    int warp = (blockIdx.x * blockDim.x + threadIdx.x) >> 5;
    int lane = threadIdx.x & 31;
    if (warp >= E) return;
    int s = src[warp];
    int d = dst[warp];
    float4 v = feat[(size_t)s * (D / 4) + lane];
    float* a = acc + (size_t)d * D + lane * 4;
    atomicAdd(a + 0, v.x);
    atomicAdd(a + 1, v.y);
    atomicAdd(a + 2, v.z);
    atomicAdd(a + 3, v.w);
    if (lane == 0) atomicAdd(cnt + d, 1);
}

// ---------------- packed fp32x2 helpers --------------------------------------
__device__ __forceinline__ u64 ffma2(u64 a, u64 b, u64 c) {
    u64 d;
    asm("fma.rn.f32x2 %0, %1, %2, %3;" : "=l"(d) : "l"(a), "l"(b), "l"(c));
    return d;
}
__device__ __forceinline__ u64 dup2(float x) {
    u64 r;
    asm("mov.b64 %0, {%1, %1};" : "=l"(r) : "f"(x));
    return r;
}
union F2U { u64 u; float2 f; };

// ---------------- GEMM with fused mean + masked bias -------------------------
// out[r][n] (+)= (acc[r][:] / max(cnt[r],1)) @ W[n][:]  + b[n] * (cnt[r] > 0)
// BM=64, BN=128, BK=16, 256 threads, thread tile 4x8, inner math = fma.rn.f32x2
#define BM 64
#define BN 128
#define BK 16
#define BMP 68   // padded lda for As (17*16B -> 16B-aligned rows, low conflicts)

template <bool ACCUM>
__global__ __launch_bounds__(256) void gemm_agg(
    float* __restrict__ out, const float* __restrict__ acc,
    const int* __restrict__ cnt, const float* __restrict__ W,
    const float* __restrict__ bias, int nrows)
{
    __shared__ __align__(16) float As[BK][BMP];
    __shared__ __align__(16) float Ws[BK][BN];

    const int tid = threadIdx.x;
    const int tx = tid & 15;        // 16 col-groups
    const int ty = tid >> 4;        // 16 row-groups
    const int row0 = blockIdx.x * BM;

    // A-loader mapping: 4 threads per row, 64B contiguous per row-chunk
    const int a_row = tid >> 2;        // 0..63
    const int a_kq  = (tid & 3) * 4;   // 0,4,8,12
    // W-loader mapping: thread handles col n, 8 consecutive k
    const int w_n  = tid & 127;
    const int w_kb = (tid >> 7) * 8;   // 0 or 8

    const int garow = row0 + a_row;
    float inv = 0.f;
    if (garow < nrows) inv = __fdividef(1.0f, fmaxf((float)cnt[garow], 1.0f));

    u64 C[4][4];
#pragma unroll
    for (int m = 0; m < 4; m++)
#pragma unroll
        for (int n = 0; n < 4; n++) C[m][n] = 0ull;

    for (int kc = 0; kc < D; kc += BK) {
        // stage A (scaled by 1/deg at load)
        float4 av = make_float4(0.f, 0.f, 0.f, 0.f);
        if (garow < nrows)
            av = *reinterpret_cast<const float4*>(acc + (size_t)garow * D + kc + a_kq);
        As[a_kq + 0][a_row] = av.x * inv;
        As[a_kq + 1][a_row] = av.y * inv;
        As[a_kq + 2][a_row] = av.z * inv;
        As[a_kq + 3][a_row] = av.w * inv;
        // stage W (transpose [n][k] -> Ws[k][n])
#pragma unroll
        for (int h = 0; h < 2; h++) {
            float4 wv = *reinterpret_cast<const float4*>(W + (size_t)w_n * D + kc + w_kb + h * 4);
            Ws[w_kb + h * 4 + 0][w_n] = wv.x;
            Ws[w_kb + h * 4 + 1][w_n] = wv.y;
            Ws[w_kb + h * 4 + 2][w_n] = wv.z;
            Ws[w_kb + h * 4 + 3][w_n] = wv.w;
        }
        __syncthreads();

#pragma unroll
        for (int k = 0; k < BK; k++) {
            float4 a4 = *reinterpret_cast<const float4*>(&As[k][ty * 4]);
            ulonglong2 wlo = *reinterpret_cast<const ulonglong2*>(&Ws[k][tx * 4]);
            ulonglong2 whi = *reinterpret_cast<const ulonglong2*>(&Ws[k][64 + tx * 4]);
            u64 ad0 = dup2(a4.x), ad1 = dup2(a4.y), ad2 = dup2(a4.z), ad3 = dup2(a4.w);
            C[0][0] = ffma2(ad0, wlo.x, C[0][0]);
            C[0][1] = ffma2(ad0, wlo.y, C[0][1]);
            C[0][2] = ffma2(ad0, whi.x, C[0][2]);
            C[0][3] = ffma2(ad0, whi.y, C[0][3]);
            C[1][0] = ffma2(ad1, wlo.x, C[1][0]);
            C[1][1] = ffma2(ad1, wlo.y, C[1][1]);
            C[1][2] = ffma2(ad1, whi.x, C[1][2]);
            C[1][3] = ffma2(ad1, whi.y, C[1][3]);
            C[2][0] = ffma2(ad2, wlo.x, C[2][0]);
            C[2][1] = ffma2(ad2, wlo.y, C[2][1]);
            C[2][2] = ffma2(ad2, whi.x, C[2][2]);
            C[2][3] = ffma2(ad2, whi.y, C[2][3]);
            C[3][0] = ffma2(ad3, wlo.x, C[3][0]);
            C[3][1] = ffma2(ad3, wlo.y, C[3][1]);
            C[3][2] = ffma2(ad3, whi.x, C[3][2]);
            C[3][3] = ffma2(ad3, whi.y, C[3][3]);
        }
        __syncthreads();
    }

    // epilogue: masked bias, optional accumulate into existing out
    float4 blo = *reinterpret_cast<const float4*>(bias + tx * 4);
    float4 bhi = *reinterpret_cast<const float4*>(bias + 64 + tx * 4);
#pragma unroll
    for (int m = 0; m < 4; m++) {
        int r = row0 + ty * 4 + m;
        if (r >= nrows) continue;
        float msk = (cnt[r] > 0) ? 1.0f : 0.0f;
        F2U c0, c1, c2, c3;
        c0.u = C[m][0]; c1.u = C[m][1]; c2.u = C[m][2]; c3.u = C[m][3];
        float4 olo = make_float4(c0.f.x + blo.x * msk, c0.f.y + blo.y * msk,
                                 c1.f.x + blo.z * msk, c1.f.y + blo.w * msk);
        float4 ohi = make_float4(c2.f.x + bhi.x * msk, c2.f.y + bhi.y * msk,
                                 c3.f.x + bhi.z * msk, c3.f.y + bhi.w * msk);
        float4* plo = reinterpret_cast<float4*>(out + (size_t)r * D + tx * 4);
        float4* phi = reinterpret_cast<float4*>(out + (size_t)r * D + 64 + tx * 4);
        if (ACCUM) {
            float4 e0 = *plo, e1 = *phi;
            olo.x += e0.x; olo.y += e0.y; olo.z += e0.z; olo.w += e0.w;
            ohi.x += e1.x; ohi.y += e1.y; ohi.z += e1.z; ohi.w += e1.w;
        }
        *plo = olo;
        *phi = ohi;
    }
}

// ---------------- launch ------------------------------------------------------
extern "C" void kernel_launch(void* const* d_in, const int* in_sizes, int n_in,
                              void* d_out, int out_size)
{
    const float* feat_user = (const float*)d_in[0];
    const float* feat_item = (const float*)d_in[1];
    const float* W_f  = (const float*)d_in[2];
    const float* b_f  = (const float*)d_in[3];
    const float* W_r  = (const float*)d_in[4];
    const float* b_r  = (const float*)d_in[5];
    const float* W_rb = (const float*)d_in[6];
    const float* b_rb = (const float*)d_in[7];
    const int* src_f  = (const int*)d_in[8];
    const int* dst_f  = (const int*)d_in[9];
    const int* src_r  = (const int*)d_in[10];
    const int* dst_r  = (const int*)d_in[11];
    const int* src_rb = (const int*)d_in[12];
    const int* dst_rb = (const int*)d_in[13];
    const int E_f  = in_sizes[8];
    const int E_r  = in_sizes[10];
    const int E_rb = in_sizes[12];

    float* out_user = (float*)d_out;
    float* out_item = (float*)d_out + (size_t)NU * D;

    float *acc_f, *acc_rb, *acc_r;
    int *cnt_f, *cnt_rb, *cnt_r;
    cudaGetSymbolAddress((void**)&acc_f,  g_acc_f);
    cudaGetSymbolAddress((void**)&acc_rb, g_acc_rb);
    cudaGetSymbolAddress((void**)&acc_r,  g_acc_r);
    cudaGetSymbolAddress((void**)&cnt_f,  g_cnt_f);
    cudaGetSymbolAddress((void**)&cnt_rb, g_cnt_rb);
    cudaGetSymbolAddress((void**)&cnt_r,  g_cnt_r);

    zero_kernel<<<1024, 256>>>();

    scatter_kernel<<<(E_f  + 7) / 8, 256>>>(
        (const float4*)feat_user, src_f, dst_f, acc_f, cnt_f, E_f);
    scatter_kernel<<<(E_rb + 7) / 8, 256>>>(
        (const float4*)feat_item, src_rb, dst_rb, acc_rb, cnt_rb, E_rb);
    scatter_kernel<<<(E_r  + 7) / 8, 256>>>(
        (const float4*)feat_user, src_r, dst_r, acc_r, cnt_r, E_r);

    const int gu = (NU + BM - 1) / BM;
    const int gi = (NI + BM - 1) / BM;
    gemm_agg<false><<<gu, 256>>>(out_user, acc_f,  cnt_f,  W_f,  b_f,  NU);
    gemm_agg<true ><<<gu, 256>>>(out_user, acc_rb, cnt_rb, W_rb, b_rb, NU);
    gemm_agg<false><<<gi, 256>>>(out_item, acc_r,  cnt_r,  W_r,  b_r,  NI);
}

// round 2
// speedup vs baseline: 1.5962x; 1.5962x over previous
#include <cuda_runtime.h>
#include <cstdint>

#define NU 100000
#define NI 100000
#define D  128
#define EMAX 810000

typedef unsigned long long u64;

// ---------------- scratch (static device allocations) ------------------------
__device__ float g_acc_f [(size_t)NU * D];   // follows:  user -> user (MEAN)
__device__ float g_acc_rb[(size_t)NU * D];   // ratedby:  item -> user (MEAN)
__device__ float g_acc_r [(size_t)NI * D];   // rates:    user -> item (MEAN)
__device__ int   g_hist_f [NU];
__device__ int   g_hist_rb[NU];
__device__ int   g_hist_r [NI];
__device__ int   g_ptr_f [NU + 1];
__device__ int   g_ptr_rb[NU + 1];
__device__ int   g_ptr_r [NI + 1];
__device__ int   g_cur_f [NU];
__device__ int   g_cur_rb[NU];
__device__ int   g_cur_r [NI];
__device__ int   g_srcl_f [EMAX];
__device__ int   g_srcl_rb[EMAX];
__device__ int   g_srcl_r [EMAX];

// ---------------- zero histograms --------------------------------------------
__global__ void zero_hist_kernel() {
    int i = blockIdx.x * blockDim.x + threadIdx.x;
    if (i < NU) { g_hist_f[i] = 0; g_hist_rb[i] = 0; g_hist_r[i] = 0; }
}

// ---------------- histogram ---------------------------------------------------
__global__ __launch_bounds__(256) void hist_kernel(
    const int* __restrict__ dst, int* __restrict__ hist, int E)
{
    int i = blockIdx.x * blockDim.x + threadIdx.x;
    if (i < E) atomicAdd(&hist[dst[i]], 1);
}

// ---------------- per-etype exclusive scan (one block per etype) --------------
__global__ __launch_bounds__(1024) void scan_kernel(int n)
{
    const int* hist; int* ptr; int* cur;
    if      (blockIdx.x == 0) { hist = g_hist_f;  ptr = g_ptr_f;  cur = g_cur_f;  }
    else if (blockIdx.x == 1) { hist = g_hist_rb; ptr = g_ptr_rb; cur = g_cur_rb; }
    else                      { hist = g_hist_r;  ptr = g_ptr_r;  cur = g_cur_r;  }

    const int T = 1024;
    int chunk = (n + T - 1) / T;
    int lo = threadIdx.x * chunk;
    int hi = lo + chunk; if (hi > n) hi = n;
    if (lo > n) lo = n;

    int s = 0;
    for (int i = lo; i < hi; i++) s += hist[i];

    __shared__ int warpsum[32];
    int lane = threadIdx.x & 31, wid = threadIdx.x >> 5;
    int incl = s;
#pragma unroll
    for (int off = 1; off < 32; off <<= 1) {
        int t = __shfl_up_sync(0xffffffffu, incl, off);
        if (lane >= off) incl += t;
    }
    if (lane == 31) warpsum[wid] = incl;
    __syncthreads();
    if (wid == 0) {
        int w = warpsum[lane];
#pragma unroll
        for (int off = 1; off < 32; off <<= 1) {
            int t = __shfl_up_sync(0xffffffffu, w, off);
            if (lane >= off) w += t;
        }
        warpsum[lane] = w;
    }
    __syncthreads();
    int excl = incl - s + (wid ? warpsum[wid - 1] : 0);
    for (int i = lo; i < hi; i++) {
        ptr[i] = excl; cur[i] = excl; excl += hist[i];
    }
    if (threadIdx.x == 0) ptr[n] = warpsum[31];
}

// ---------------- permute: build per-dst src lists ----------------------------
__global__ __launch_bounds__(256) void permute_kernel(
    const int* __restrict__ src, const int* __restrict__ dst,
    int* __restrict__ cur, int* __restrict__ srclist, int E)
{
    int i = blockIdx.x * blockDim.x + threadIdx.x;
    if (i < E) {
        int d = dst[i];
        int p = atomicAdd(&cur[d], 1);
        srclist[p] = src[i];
    }
}

// ---------------- gather: one warp per dst node, mean of feat[src] ------------
__global__ __launch_bounds__(256) void gather_kernel(
    const float4* __restrict__ feat, const int* __restrict__ ptr,
    const int* __restrict__ srclist, float4* __restrict__ acc, int n)
{
    int warp = (blockIdx.x * 256 + threadIdx.x) >> 5;
    int lane = threadIdx.x & 31;
    if (warp >= n) return;
    int beg = __ldg(&ptr[warp]);
    int end = __ldg(&ptr[warp + 1]);
    int deg = end - beg;
    float4 s = make_float4(0.f, 0.f, 0.f, 0.f);
    int e = beg;
    for (; e + 3 < end; e += 4) {
        int s0 = __ldg(&srclist[e + 0]);
        int s1 = __ldg(&srclist[e + 1]);
        int s2 = __ldg(&srclist[e + 2]);
        int s3 = __ldg(&srclist[e + 3]);
        float4 v0 = feat[(size_t)s0 * 32 + lane];
        float4 v1 = feat[(size_t)s1 * 32 + lane];
        float4 v2 = feat[(size_t)s2 * 32 + lane];
        float4 v3 = feat[(size_t)s3 * 32 + lane];
        s.x += (v0.x + v1.x) + (v2.x + v3.x);
        s.y += (v0.y + v1.y) + (v2.y + v3.y);
        s.z += (v0.z + v1.z) + (v2.z + v3.z);
        s.w += (v0.w + v1.w) + (v2.w + v3.w);
    }
    for (; e < end; e++) {
        int s0 = __ldg(&srclist[e]);
        float4 v0 = feat[(size_t)s0 * 32 + lane];
        s.x += v0.x; s.y += v0.y; s.z += v0.z; s.w += v0.w;
    }
    float inv = __fdividef(1.0f, (float)(deg > 0 ? deg : 1));
    s.x *= inv; s.y *= inv; s.z *= inv; s.w *= inv;
    acc[(size_t)warp * 32 + lane] = s;
}

// ---------------- packed fp32x2 helpers --------------------------------------
__device__ __forceinline__ u64 ffma2(u64 a, u64 b, u64 c) {
    u64 d;
    asm("fma.rn.f32x2 %0, %1, %2, %3;" : "=l"(d) : "l"(a), "l"(b), "l"(c));
    return d;
}
__device__ __forceinline__ u64 dup2(float x) {
    u64 r;
    asm("mov.b64 %0, {%1, %1};" : "=l"(r) : "f"(x));
    return r;
}
union F2U { u64 u; float2 f; };

// ---------------- GEMM: out[r][n] (+)= mean[r][:] @ W[n][:] + b[n]*(cnt>0) ----
#define BM 64
#define BN 128
#define BK 16
#define BMP 68

template <bool ACCUM>
__global__ __launch_bounds__(256) void gemm_agg(
    float* __restrict__ out, const float* __restrict__ acc,
    const int* __restrict__ cnt, const float* __restrict__ W,
    const float* __restrict__ bias, int nrows)
{
    __shared__ __align__(16) float As[BK][BMP];
    __shared__ __align__(16) float Ws[BK][BN];

    const int tid = threadIdx.x;
    const int tx = tid & 15;
    const int ty = tid >> 4;
    const int row0 = blockIdx.x * BM;

    const int a_row = tid >> 2;
    const int a_kq  = (tid & 3) * 4;
    const int w_n  = tid & 127;
    const int w_kb = (tid >> 7) * 8;

    const int garow = row0 + a_row;

    u64 C[4][4];
#pragma unroll
    for (int m = 0; m < 4; m++)
#pragma unroll
        for (int n = 0; n < 4; n++) C[m][n] = 0ull;

    for (int kc = 0; kc < D; kc += BK) {
        float4 av = make_float4(0.f, 0.f, 0.f, 0.f);
        if (garow < nrows)
            av = *reinterpret_cast<const float4*>(acc + (size_t)garow * D + kc + a_kq);
        As[a_kq + 0][a_row] = av.x;
        As[a_kq + 1][a_row] = av.y;
        As[a_kq + 2][a_row] = av.z;
        As[a_kq + 3][a_row] = av.w;
#pragma unroll
        for (int h = 0; h < 2; h++) {
            float4 wv = *reinterpret_cast<const float4*>(W + (size_t)w_n * D + kc + w_kb + h * 4);
            Ws[w_kb + h * 4 + 0][w_n] = wv.x;
            Ws[w_kb + h * 4 + 1][w_n] = wv.y;
            Ws[w_kb + h * 4 + 2][w_n] = wv.z;
            Ws[w_kb + h * 4 + 3][w_n] = wv.w;
        }
        __syncthreads();

#pragma unroll
        for (int k = 0; k < BK; k++) {
            float4 a4 = *reinterpret_cast<const float4*>(&As[k][ty * 4]);
            ulonglong2 wlo = *reinterpret_cast<const ulonglong2*>(&Ws[k][tx * 4]);
            ulonglong2 whi = *reinterpret_cast<const ulonglong2*>(&Ws[k][64 + tx * 4]);
            u64 ad0 = dup2(a4.x), ad1 = dup2(a4.y), ad2 = dup2(a4.z), ad3 = dup2(a4.w);
            C[0][0] = ffma2(ad0, wlo.x, C[0][0]);
            C[0][1] = ffma2(ad0, wlo.y, C[0][1]);
            C[0][2] = ffma2(ad0, whi.x, C[0][2]);
            C[0][3] = ffma2(ad0, whi.y, C[0][3]);
            C[1][0] = ffma2(ad1, wlo.x, C[1][0]);
            C[1][1] = ffma2(ad1, wlo.y, C[1][1]);
            C[1][2] = ffma2(ad1, whi.x, C[1][2]);
            C[1][3] = ffma2(ad1, whi.y, C[1][3]);
            C[2][0] = ffma2(ad2, wlo.x, C[2][0]);
            C[2][1] = ffma2(ad2, wlo.y, C[2][1]);
            C[2][2] = ffma2(ad2, whi.x, C[2][2]);
            C[2][3] = ffma2(ad2, whi.y, C[2][3]);
            C[3][0] = ffma2(ad3, wlo.x, C[3][0]);
            C[3][1] = ffma2(ad3, wlo.y, C[3][1]);
            C[3][2] = ffma2(ad3, whi.x, C[3][2]);
            C[3][3] = ffma2(ad3, whi.y, C[3][3]);
        }
        __syncthreads();
    }

    float4 blo = *reinterpret_cast<const float4*>(bias + tx * 4);
    float4 bhi = *reinterpret_cast<const float4*>(bias + 64 + tx * 4);
#pragma unroll
    for (int m = 0; m < 4; m++) {
        int r = row0 + ty * 4 + m;
        if (r >= nrows) continue;
        float msk = (cnt[r] > 0) ? 1.0f : 0.0f;
        F2U c0, c1, c2, c3;
        c0.u = C[m][0]; c1.u = C[m][1]; c2.u = C[m][2]; c3.u = C[m][3];
        float4 olo = make_float4(c0.f.x + blo.x * msk, c0.f.y + blo.y * msk,
                                 c1.f.x + blo.z * msk, c1.f.y + blo.w * msk);
        float4 ohi = make_float4(c2.f.x + bhi.x * msk, c2.f.y + bhi.y * msk,
                                 c3.f.x + bhi.z * msk, c3.f.y + bhi.w * msk);
        float4* plo = reinterpret_cast<float4*>(out + (size_t)r * D + tx * 4);
        float4* phi = reinterpret_cast<float4*>(out + (size_t)r * D + 64 + tx * 4);
        if (ACCUM) {
            float4 e0 = *plo, e1 = *phi;
            olo.x += e0.x; olo.y += e0.y; olo.z += e0.z; olo.w += e0.w;
            ohi.x += e1.x; ohi.y += e1.y; ohi.z += e1.z; ohi.w += e1.w;
        }
        *plo = olo;
        *phi = ohi;
    }
}

// ---------------- launch ------------------------------------------------------
extern "C" void kernel_launch(void* const* d_in, const int* in_sizes, int n_in,
                              void* d_out, int out_size)
{
    const float* feat_user = (const float*)d_in[0];
    const float* feat_item = (const float*)d_in[1];
    const float* W_f  = (const float*)d_in[2];
    const float* b_f  = (const float*)d_in[3];
    const float* W_r  = (const float*)d_in[4];
    const float* b_r  = (const float*)d_in[5];
    const float* W_rb = (const float*)d_in[6];
    const float* b_rb = (const float*)d_in[7];
    const int* src_f  = (const int*)d_in[8];
    const int* dst_f  = (const int*)d_in[9];
    const int* src_r  = (const int*)d_in[10];
    const int* dst_r  = (const int*)d_in[11];
    const int* src_rb = (const int*)d_in[12];
    const int* dst_rb = (const int*)d_in[13];
    const int E_f  = in_sizes[8];
    const int E_r  = in_sizes[10];
    const int E_rb = in_sizes[12];

    float* out_user = (float*)d_out;
    float* out_item = (float*)d_out + (size_t)NU * D;

    float *acc_f, *acc_rb, *acc_r;
    int *hist_f, *hist_rb, *hist_r;
    int *ptr_f, *ptr_rb, *ptr_r;
    int *cur_f, *cur_rb, *cur_r;
    int *srcl_f, *srcl_rb, *srcl_r;
    cudaGetSymbolAddress((void**)&acc_f,  g_acc_f);
    cudaGetSymbolAddress((void**)&acc_rb, g_acc_rb);
    cudaGetSymbolAddress((void**)&acc_r,  g_acc_r);
    cudaGetSymbolAddress((void**)&hist_f,  g_hist_f);
    cudaGetSymbolAddress((void**)&hist_rb, g_hist_rb);
    cudaGetSymbolAddress((void**)&hist_r,  g_hist_r);
    cudaGetSymbolAddress((void**)&ptr_f,  g_ptr_f);
    cudaGetSymbolAddress((void**)&ptr_rb, g_ptr_rb);
    cudaGetSymbolAddress((void**)&ptr_r,  g_ptr_r);
    cudaGetSymbolAddress((void**)&cur_f,  g_cur_f);
    cudaGetSymbolAddress((void**)&cur_rb, g_cur_rb);
    cudaGetSymbolAddress((void**)&cur_r,  g_cur_r);
    cudaGetSymbolAddress((void**)&srcl_f,  g_srcl_f);
    cudaGetSymbolAddress((void**)&srcl_rb, g_srcl_rb);
    cudaGetSymbolAddress((void**)&srcl_r,  g_srcl_r);

    // 1) zero histograms
    zero_hist_kernel<<<(NU + 255) / 256, 256>>>();

    // 2) histograms
    hist_kernel<<<(E_f  + 255) / 256, 256>>>(dst_f,  hist_f,  E_f);
    hist_kernel<<<(E_rb + 255) / 256, 256>>>(dst_rb, hist_rb, E_rb);
    hist_kernel<<<(E_r  + 255) / 256, 256>>>(dst_r,  hist_r,  E_r);

    // 3) exclusive scans (3 etypes, one block each)
    scan_kernel<<<3, 1024>>>(NU);

    // 4) build per-dst src lists
    permute_kernel<<<(E_f  + 255) / 256, 256>>>(src_f,  dst_f,  cur_f,  srcl_f,  E_f);
    permute_kernel<<<(E_rb + 255) / 256, 256>>>(src_rb, dst_rb, cur_rb, srcl_rb, E_rb);
    permute_kernel<<<(E_r  + 255) / 256, 256>>>(src_r,  dst_r,  cur_r,  srcl_r,  E_r);

    // 5) gather means
    const int gw = (NU * 32 + 255) / 256;   // one warp per node
    gather_kernel<<<gw, 256>>>((const float4*)feat_user, ptr_f,  srcl_f,
                               (float4*)acc_f,  NU);
    gather_kernel<<<gw, 256>>>((const float4*)feat_item, ptr_rb, srcl_rb,
                               (float4*)acc_rb, NU);
    gather_kernel<<<gw, 256>>>((const float4*)feat_user, ptr_r,  srcl_r,
                               (float4*)acc_r,  NI);

    // 6) GEMMs with fused bias mask + etype combine
    const int gu = (NU + BM - 1) / BM;
    const int gi = (NI + BM - 1) / BM;
    gemm_agg<false><<<gu, 256>>>(out_user, acc_f,  hist_f,  W_f,  b_f,  NU);
    gemm_agg<true ><<<gu, 256>>>(out_user, acc_rb, hist_rb, W_rb, b_rb, NU);
    gemm_agg<false><<<gi, 256>>>(out_item, acc_r,  hist_r,  W_r,  b_r,  NI);
}